// round 7
// baseline (speedup 1.0000x reference)
#include <cuda_runtime.h>
#include <cstdint>

// ---------------------------------------------------------------------------
// SphericalHarmonicTransform, scalar 1 point/thread, 12 warps/SM occupancy,
// fused deterministic final reduction.
// Replicates the reference's exact (buggy) complex-power recurrence.
// ---------------------------------------------------------------------------

#define NBLK 444            // 148 SMs x 3 CTAs, one full wave
#define NTHR 128
#define NWARP (NTHR / 32)
#define NOUT 81

__device__ float g_scratch[NOUT * NBLK];
__device__ int   g_count = 0;

// ---- compile-time helpers -------------------------------------------------
__host__ __device__ constexpr double dfact(int n) {
    double r = 1.0;
    for (int i = 2; i <= n; ++i) r *= (double)i;
    return r;
}
__host__ __device__ constexpr double csqrt(double x) {
    double g = x > 1.0 ? x : 1.0;
    for (int i = 0; i < 128; ++i) g = 0.5 * (g + x / g);
    return g;
}
constexpr double PI_REF = 3.14159;                    // reference's PI
constexpr float  PIC    = 0.62831853071795864769f;    // pi/RCUT (true pi)

template <int I> struct ic { static constexpr int v = I; };
template <int S, int E, class F>
__device__ __forceinline__ void sfor(F f) {
    if constexpr (S < E) { f(ic<S>{}); sfor<S + 1, E>(f); }
}

__global__ void __launch_bounds__(NTHR, 3)
sht_main(const float* __restrict__ pos, int n, float* __restrict__ out)
{
    float acc[NOUT];
#pragma unroll
    for (int j = 0; j < NOUT; ++j) acc[j] = 0.0f;

    const int stride = NBLK * NTHR;

    for (int i = blockIdx.x * NTHR + threadIdx.x; i < n; i += stride) {
        const float x = pos[3 * i + 0];
        const float y = pos[3 * i + 1];
        const float z = pos[3 * i + 2];

        // ---- head: cutoff + 1/norm ----------------------------------------
        const float n2 = fmaf(x, x, fmaf(y, y, z * z));
        const float nm = sqrtf(n2);
        float cut = 0.5f * (__cosf(nm * PIC) + 1.0f);
        float safe = nm;
        if (nm > 5.0f) cut = 0.0f;              // RCUT
        if (!(nm > 0.0f)) { cut = 0.0f; safe = 1.0f; }
        const float inv  = __fdividef(1.0f, safe);
        const float cutz = cut * z;

        const float ar = -0.5f * x, ai = -0.5f * y;   // xp
        const float br =  0.5f * x;                    // xm (bi == ai)

        // ---- p1 = powers of (ar, ai), reference's buggy chain -------------
        float p1r[9], p1i[9];
        p1r[1] = ar; p1i[1] = ai;
        p1r[2] = fmaf(-ai, ai, ar * ar);
        p1i[2] = 2.0f * ar * ai;
        {
            float cr = ar, ci = ai;
            {   // iter^1 (chain state; NOT equal to p1[2])
                float nr = fmaf(-ai, ci, ar * cr);
                ci = fmaf(ai, nr, ar * ci);            // uses NEW real
                cr = nr;
            }
#pragma unroll
            for (int k = 3; k <= 8; ++k) {
                float nr = fmaf(-ai, ci, ar * cr);
                ci = fmaf(ai, nr, ar * ci);
                cr = nr;
                p1r[k] = cr; p1i[k] = ci;
            }
        }

        // ---- p2 = powers of (br, ai) --------------------------------------
        float p2r[5], p2i[5];
        p2r[1] = br;       p2i[1] = ai;
        p2r[2] = p1r[2];   p2i[2] = -p1i[2];
        {
            float cr = br, ci = ai;
            {   // iter^1
                float nr = fmaf(-ai, ci, br * cr);
                ci = fmaf(ai, nr, br * ci);
                cr = nr;
            }
#pragma unroll
            for (int k = 3; k <= 4; ++k) {
                float nr = fmaf(-ai, ci, br * cr);
                ci = fmaf(ai, nr, br * ci);
                cr = nr;
                p2r[k] = cr; p2i[k] = ci;
            }
        }

        float sq1[9];
#pragma unroll
        for (int p = 1; p < 9; ++p) sq1[p] = p1r[p] * p1r[p];

        // ---- all (l, m, p) terms; imm-form FFMA sums ----------------------
        float WL = cutz;                         // cut*z * inv^l (l = 0)
        sfor<0, 9>([&](auto Lc) {
            constexpr int l = decltype(Lc)::v;
            sfor<0, l + 1>([&](auto Mc) {
                constexpr int m    = decltype(Mc)::v;
                constexpr int pmax = (l + m) / 2;
                float sr = 0.0f, si = 0.0f;
                sfor<m, pmax + 1>([&](auto Pc) {
                    constexpr int p = decltype(Pc)::v;
                    constexpr int q = p - m;
                    constexpr int s = l - p - q;
                    constexpr double kl  = csqrt((2.0 * l + 1.0) / (4.0 * PI_REF));
                    constexpr double ff  = csqrt(dfact(l + m) * dfact(l - m));
                    constexpr double fac = (m == 0) ? 1.0
                        : 1.41421356237309514547 * ((m & 1) ? -1.0 : 1.0);
                    constexpr float c =
                        (float)(kl * ff * fac /
                                (dfact(p) * dfact(q) * dfact(s)));
                    if constexpr (p == 0) {
                        sr += c;                          // zr=1, zi=0
                    } else if constexpr (q == 0) {
                        sr = fmaf(sq1[p], c, sr);         // zr = p1r^2
                        if constexpr (m > 0)
                            si = fmaf(p1i[p], c, si);     // zi = p1i
                    } else {
                        const float zr = fmaf(-p2i[q], p2i[q], sq1[p]);
                        sr = fmaf(zr, c, sr);
                        if constexpr (m > 0) {
                            const float zi =
                                fmaf(p1r[p], p2i[q], p1i[p] * p2r[q]);
                            si = fmaf(zi, c, si);
                        }
                    }
                });
                if constexpr (m == 0) {
                    acc[l * l + l] = fmaf(sr, WL, acc[l * l + l]);
                } else {
                    acc[l * l + l - m] = fmaf(si, WL, acc[l * l + l - m]);
                    acc[l * l + l + m] = fmaf(sr, WL, acc[l * l + l + m]);
                }
            });
            WL *= inv;
        });
    }

    // ---- block reduction ---------------------------------------------------
    __shared__ float sred[NOUT * NWARP];
    const int lane = threadIdx.x & 31;
    const int warp = threadIdx.x >> 5;
#pragma unroll
    for (int j = 0; j < NOUT; ++j) {
        float v = acc[j];
        v += __shfl_down_sync(0xffffffffu, v, 16);
        v += __shfl_down_sync(0xffffffffu, v, 8);
        v += __shfl_down_sync(0xffffffffu, v, 4);
        v += __shfl_down_sync(0xffffffffu, v, 2);
        v += __shfl_down_sync(0xffffffffu, v, 1);
        if (lane == 0) sred[j * NWARP + warp] = v;
    }
    __syncthreads();
    if (threadIdx.x < NOUT) {
        float s = 0.0f;
#pragma unroll
        for (int w = 0; w < NWARP; ++w) s += sred[threadIdx.x * NWARP + w];
        g_scratch[threadIdx.x * NBLK + blockIdx.x] = s;
    }

    // ---- last block performs the deterministic final reduction -------------
    __syncthreads();
    __shared__ int s_last;
    if (threadIdx.x == 0) {
        __threadfence();
        s_last = (atomicAdd(&g_count, 1) == NBLK - 1);
    }
    __syncthreads();
    if (s_last) {
        __threadfence();
        for (int j = warp; j < NOUT; j += NWARP) {
            float v = 0.0f;
            for (int k = lane; k < NBLK; k += 32)
                v += __ldcg(&g_scratch[j * NBLK + k]);
            v += __shfl_down_sync(0xffffffffu, v, 16);
            v += __shfl_down_sync(0xffffffffu, v, 8);
            v += __shfl_down_sync(0xffffffffu, v, 4);
            v += __shfl_down_sync(0xffffffffu, v, 2);
            v += __shfl_down_sync(0xffffffffu, v, 1);
            if (lane == 0) out[j] = v;
        }
        if (threadIdx.x == 0) g_count = 0;   // reset for next graph replay
    }
}

extern "C" void kernel_launch(void* const* d_in, const int* in_sizes, int n_in,
                              void* d_out, int out_size)
{
    const float* pos = (const float*)d_in[0];
    const int n = in_sizes[0] / 3;
    sht_main<<<NBLK, NTHR>>>(pos, n, (float*)d_out);
}